// round 3
// baseline (speedup 1.0000x reference)
#include <cuda_runtime.h>
#include <math.h>

// Problem constants
#define NB 8
#define NT 1024
#define NC 8
#define NF 513
#define NA 320
#define NSPLIT 4

// Scratch (device globals; no runtime allocation). float4 types force 16B align.
__device__ float4 g_ms4[NB*NF*NT/4];        // normalized speech mask (B,F,T)
__device__ float4 g_mn4[NB*NF*NT/4];        // normalized noise mask  (B,F,T)
__device__ float4 g_part[NSPLIT*NB*NF*36];  // psd partials (sr,si,nr,ni) per pair
__device__ float2 g_psd_s[NB*NF*64];        // (B,F,C,C)
__device__ float2 g_psd_n[NB*NF*64];
__device__ float  g_e[NB*NC];
__device__ float2 g_bf[NB*NF*NC];           // beamformer vector (B,F,C)

// pair p -> (i,j), i<=j, j-major enumeration
__device__ const int d_pi[36] = {0, 0,1, 0,1,2, 0,1,2,3, 0,1,2,3,4,
                                 0,1,2,3,4,5, 0,1,2,3,4,5,6, 0,1,2,3,4,5,6,7};
__device__ const int d_pj[36] = {0, 1,1, 2,2,2, 3,3,3,3, 4,4,4,4,4,
                                 5,5,5,5,5,5, 6,6,6,6,6,6,6, 7,7,7,7,7,7,7,7};

// ---- packed f32x2 helpers (sm_103a keeps f32x2 math; FP32 REDUX is gone) ----
__device__ __forceinline__ unsigned long long pk2(float lo, float hi) {
    unsigned long long r;
    asm("mov.b64 %0, {%1, %2};" : "=l"(r) : "f"(lo), "f"(hi));
    return r;
}
__device__ __forceinline__ unsigned long long mul2(unsigned long long a, unsigned long long b) {
    unsigned long long r;
    asm("mul.rn.f32x2 %0, %1, %2;" : "=l"(r) : "l"(a), "l"(b));
    return r;
}
__device__ __forceinline__ unsigned long long fma2(unsigned long long a, unsigned long long b,
                                                   unsigned long long c) {
    unsigned long long r;
    asm("fma.rn.f32x2 %0, %1, %2, %3;" : "=l"(r) : "l"(a), "l"(b), "l"(c));
    return r;
}
__device__ __forceinline__ void unpk2(unsigned long long v, float& lo, float& hi) {
    asm("mov.b64 {%0, %1}, %2;" : "=f"(lo), "=f"(hi) : "l"(v));
}
__device__ __forceinline__ float warp_sum(float v) {
#pragma unroll
    for (int d = 16; d >= 1; d >>= 1)
        v += __shfl_xor_sync(0xffffffffu, v, d);
    return v;
}

// ---------------------------------------------------------------------------
// Kernel 1: masks -> channel mean, clip, normalize over time (float4)
// grid = B*F blocks, 256 threads, 4 t per thread
// ---------------------------------------------------------------------------
__global__ __launch_bounds__(256)
void mask_norm_kernel(const float* __restrict__ mask_s,
                      const float* __restrict__ mask_n) {
    int bf  = blockIdx.x;                 // b*NF + f
    int tid = threadIdx.x;
    const float4* ms4 = (const float4*)(mask_s + (size_t)bf * NC * NT);
    const float4* mn4 = (const float4*)(mask_n + (size_t)bf * NC * NT);

    float4 vs = make_float4(0.f, 0.f, 0.f, 0.f);
    float4 vn = make_float4(0.f, 0.f, 0.f, 0.f);
#pragma unroll
    for (int c = 0; c < 8; c++) {
        float4 a = ms4[c * 256 + tid];
        vs.x += fmaxf(a.x, 1e-6f); vs.y += fmaxf(a.y, 1e-6f);
        vs.z += fmaxf(a.z, 1e-6f); vs.w += fmaxf(a.w, 1e-6f);
        float4 b = mn4[c * 256 + tid];
        vn.x += fmaxf(b.x, 1e-6f); vn.y += fmaxf(b.y, 1e-6f);
        vn.z += fmaxf(b.z, 1e-6f); vn.w += fmaxf(b.w, 1e-6f);
    }
    vs.x *= 0.125f; vs.y *= 0.125f; vs.z *= 0.125f; vs.w *= 0.125f;
    vn.x *= 0.125f; vn.y *= 0.125f; vn.z *= 0.125f; vn.w *= 0.125f;

    float sums = warp_sum(vs.x + vs.y + vs.z + vs.w);
    float sumn = warp_sum(vn.x + vn.y + vn.z + vn.w);
    __shared__ float reds[8], redn[8];
    int lane = tid & 31, w = tid >> 5;
    if (lane == 0) { reds[w] = sums; redn[w] = sumn; }
    __syncthreads();
    float ts = 0.f, tn = 0.f;
#pragma unroll
    for (int i = 0; i < 8; i++) { ts += reds[i]; tn += redn[i]; }
    float rs = 1.0f / (ts + 1e-15f);
    float rn = 1.0f / (tn + 1e-15f);

    float4* oms = g_ms4 + (size_t)bf * 256;
    float4* omn = g_mn4 + (size_t)bf * 256;
    oms[tid] = make_float4(vs.x * rs, vs.y * rs, vs.z * rs, vs.w * rs);
    omn[tid] = make_float4(vn.x * rn, vn.y * rn, vn.z * rn, vn.w * rn);
}

// ---------------------------------------------------------------------------
// Kernel 2: PSD accumulation with packed f32x2 math.
// grid = (57, B, NSPLIT), 288 threads (9 warps). Warp w owns f = fblk*9 + w,
// time slice z*256..+256. Writes per-(b,f,pair) partials.
// ---------------------------------------------------------------------------
__global__ __launch_bounds__(288, 1)
void psd_kernel(const float2* __restrict__ data) {
    __shared__ float2 tile[9][8][65];     // [f_local][c][t] (+1 pad)
    int fblk = blockIdx.x, b = blockIdx.y, z = blockIdx.z;
    int f0 = fblk * 9;
    int tid = threadIdx.x, w = tid >> 5, lane = tid & 31;
    int f = f0 + w;

    unsigned long long acc_s[36], acc_n[36];
#pragma unroll
    for (int p = 0; p < 36; p++) { acc_s[p] = 0ull; acc_n[p] = 0ull; }

    const float2* dbase = data + (size_t)b * NT * NC * NF;
    const float* msb = ((const float*)g_ms4) + ((size_t)b * NF + f) * NT;
    const float* mnb = ((const float*)g_mn4) + ((size_t)b * NF + f) * NT;

    // cooperative load decomposition: 4608 float2 per 64-t chunk, 16/thread
    int r     = tid % 72;
    int c_ld  = r / 9;
    int fl_ld = r % 9;
    int tb_ld = tid / 72;

    int tbase = z * (NT / NSPLIT);
    for (int t0 = tbase; t0 < tbase + NT / NSPLIT; t0 += 64) {
#pragma unroll
        for (int it = 0; it < 16; it++) {
            int tt = tb_ld + it * 4;
            tile[fl_ld][c_ld][tt] =
                dbase[((size_t)(t0 + tt) * NC + c_ld) * NF + f0 + fl_ld];
        }
        __syncthreads();
#pragma unroll
        for (int s = 0; s < 2; s++) {
            int tt = lane + s * 32;
            float msv = msb[t0 + tt];
            float mnv = mnb[t0 + tt];
            unsigned long long ms2 = pk2(msv, msv);
            unsigned long long mn2 = pk2(mnv, mnv);
            float2 x[8];
#pragma unroll
            for (int c = 0; c < 8; c++) x[c] = tile[w][c][tt];
            unsigned long long a_[8], bb_[8];
#pragma unroll
            for (int c = 0; c < 8; c++) {
                a_[c]  = pk2(x[c].x, x[c].y);
                bb_[c] = pk2(x[c].y, -x[c].x);
            }
            int p = 0;
#pragma unroll
            for (int j = 0; j < 8; j++) {
                unsigned long long rr = pk2(x[j].x, x[j].x);
                unsigned long long ii = pk2(x[j].y, x[j].y);
#pragma unroll
                for (int i = 0; i <= j; i++) {
                    // (pre,pim) = (ri,ii_)*(rj,rj) + (ii,-ri)*(ij,ij)
                    unsigned long long pv = fma2(bb_[i], ii, mul2(a_[i], rr));
                    acc_s[p] = fma2(ms2, pv, acc_s[p]);
                    acc_n[p] = fma2(mn2, pv, acc_n[p]);
                    p++;
                }
            }
        }
        __syncthreads();
    }

    // warp butterfly reduction; lane 0 writes partial
    float4* part = g_part + (((size_t)z * NB + b) * NF + f) * 36;
#pragma unroll
    for (int q = 0; q < 36; q++) {
        float sr, si, nr, ni;
        unpk2(acc_s[q], sr, si);
        unpk2(acc_n[q], nr, ni);
#pragma unroll
        for (int d = 16; d >= 1; d >>= 1) {
            sr += __shfl_xor_sync(0xffffffffu, sr, d);
            si += __shfl_xor_sync(0xffffffffu, si, d);
            nr += __shfl_xor_sync(0xffffffffu, nr, d);
            ni += __shfl_xor_sync(0xffffffffu, ni, d);
        }
        if (lane == 0) part[q] = make_float4(sr, si, nr, ni);
    }
}

// ---------------------------------------------------------------------------
// Kernel 2b: combine NSPLIT partials -> full Hermitian PSD matrices
// ---------------------------------------------------------------------------
__global__ void combine_kernel() {
    int idx = blockIdx.x * 256 + threadIdx.x;   // over NB*NF*36
    if (idx >= NB * NF * 36) return;
    int bf = idx / 36, q = idx - bf * 36;
    float4 v = make_float4(0.f, 0.f, 0.f, 0.f);
#pragma unroll
    for (int z = 0; z < NSPLIT; z++) {
        float4 pz = g_part[((size_t)z * NB * NF + bf) * 36 + q];
        v.x += pz.x; v.y += pz.y; v.z += pz.z; v.w += pz.w;
    }
    int i = d_pi[q], j = d_pj[q];
    float2* ps = g_psd_s + (size_t)bf * 64;
    float2* pn = g_psd_n + (size_t)bf * 64;
    ps[i * 8 + j] = make_float2(v.x, v.y);
    pn[i * 8 + j] = make_float2(v.z, v.w);
    if (i != j) {
        ps[j * 8 + i] = make_float2(v.x, -v.y);
        pn[j * 8 + i] = make_float2(v.z, -v.w);
    }
}

// ---------------------------------------------------------------------------
// Kernel 3: attention reference feature + MLP -> e (B,C)
// grid = B*C blocks, 320 threads (one per hidden unit)
// ---------------------------------------------------------------------------
__global__ __launch_bounds__(320)
void attn_kernel(const float* __restrict__ W_psd,
                 const float* __restrict__ b_psd,
                 const float* __restrict__ w_gvec,
                 const float* __restrict__ b_gvec) {
    int b = blockIdx.x >> 3;
    int c = blockIdx.x & 7;
    __shared__ float feat[NF];
    for (int f = threadIdx.x; f < NF; f += 320) {
        const float2* row = g_psd_s + (((size_t)b * NF + f) * 8 + c) * 8;
        float sr = 0.f, si = 0.f;
#pragma unroll
        for (int e = 0; e < 8; e++) {
            if (e != c) { sr += row[e].x; si += row[e].y; }
        }
        feat[f] = sqrtf(sr * sr + si * si) * (1.0f / 7.0f);
    }
    __syncthreads();

    int a = threadIdx.x;                  // exactly NA threads
    float h = b_psd[a];
#pragma unroll 8
    for (int f = 0; f < NF; f++) h += feat[f] * W_psd[f * NA + a];
    float part = warp_sum(tanhf(h) * w_gvec[a]);

    __shared__ float red[10];
    int lane = threadIdx.x & 31, w = threadIdx.x >> 5;
    if (lane == 0) red[w] = part;
    __syncthreads();
    if (threadIdx.x == 0) {
        float tot = 0.f;
#pragma unroll
        for (int i = 0; i < 10; i++) tot += red[i];
        g_e[b * NC + c] = tot + b_gvec[0];
    }
}

// ---------------------------------------------------------------------------
// Kernel 4: MVDR solve + fused softmax, half-warp (16 lanes) per (b,f).
// ---------------------------------------------------------------------------
__global__ void mvdr_kernel() {
    int gt = blockIdx.x * blockDim.x + threadIdx.x;
    int gw = gt >> 4;                 // problem id = b*NF + f
    int hl = threadIdx.x & 15;        // column within augmented matrix
    if (gw >= NB * NF) return;        // whole warps exit together
    int b = gw / NF;

    // fused softmax over channels (both 8-halves compute same values)
    float ev = g_e[b * NC + (hl & 7)];
    float mx = ev;
#pragma unroll
    for (int d = 4; d >= 1; d >>= 1)
        mx = fmaxf(mx, __shfl_xor_sync(0xffffffffu, mx, d, 16));
    float ex = expf(2.0f * (ev - mx));
    float ssum = ex;
#pragma unroll
    for (int d = 4; d >= 1; d >>= 1)
        ssum += __shfl_xor_sync(0xffffffffu, ssum, d, 16);
    float uc = (hl >= 8) ? (ex / ssum) : 0.0f;

    const float2* Pn = g_psd_n + (size_t)gw * 64;
    const float2* Ps = g_psd_s + (size_t)gw * 64;

    float2 m[8];
#pragma unroll
    for (int r0 = 0; r0 < 8; r0++)
        m[r0] = (hl < 8) ? Pn[r0 * 8 + hl] : Ps[r0 * 8 + (hl - 8)];
    if (hl < 8) {
#pragma unroll
        for (int r0 = 0; r0 < 8; r0++)
            if (r0 == hl) m[r0].x += 1e-15f;
    }

#pragma unroll
    for (int k = 0; k < 8; k++) {
        float pr = __shfl_sync(0xffffffffu, m[k].x, k, 16);
        float pi = __shfl_sync(0xffffffffu, m[k].y, k, 16);
        float den = pr * pr + pi * pi;
        float id  = 1.0f / den;
        float ir  =  pr * id;
        float ii  = -pi * id;
        float nr = m[k].x * ir - m[k].y * ii;
        float ni = m[k].x * ii + m[k].y * ir;
        m[k].x = nr; m[k].y = ni;
#pragma unroll
        for (int i = 0; i < 8; i++) {
            if (i == k) continue;
            float fr = __shfl_sync(0xffffffffu, m[i].x, k, 16);
            float fi = __shfl_sync(0xffffffffu, m[i].y, k, 16);
            m[i].x -= fr * m[k].x - fi * m[k].y;
            m[i].y -= fr * m[k].y + fi * m[k].x;
        }
    }

    // trace of num (lanes 8..15 hold columns; diag entry = row (hl-8))
    float tr_r = 0.f, tr_i = 0.f;
#pragma unroll
    for (int d = 0; d < 8; d++) {
        if (hl == 8 + d) { tr_r = m[d].x; tr_i = m[d].y; }
    }
#pragma unroll
    for (int d = 8; d >= 1; d >>= 1) {
        tr_r += __shfl_xor_sync(0xffffffffu, tr_r, d, 16);
        tr_i += __shfl_xor_sync(0xffffffffu, tr_i, d, 16);
    }
    tr_r += 1e-15f;
    float tden = tr_r * tr_r + tr_i * tr_i;
    float tid_ = 1.0f / tden;
    float itr_r =  tr_r * tid_;
    float itr_i = -tr_i * tid_;

    float pr_[8], pi_[8];
#pragma unroll
    for (int e = 0; e < 8; e++) { pr_[e] = m[e].x * uc; pi_[e] = m[e].y * uc; }
#pragma unroll
    for (int e = 0; e < 8; e++) {
#pragma unroll
        for (int d = 8; d >= 1; d >>= 1) {
            pr_[e] += __shfl_xor_sync(0xffffffffu, pr_[e], d, 16);
            pi_[e] += __shfl_xor_sync(0xffffffffu, pi_[e], d, 16);
        }
    }
    if (hl == 0) {
        float2* out = g_bf + (size_t)gw * NC;
#pragma unroll
        for (int e = 0; e < 8; e++) {
            out[e] = make_float2(pr_[e] * itr_r - pi_[e] * itr_i,
                                 pr_[e] * itr_i + pi_[e] * itr_r);
        }
    }
}

// ---------------------------------------------------------------------------
// Kernel 5: apply beamformer. enh[b,t,f] = sum_c conj(bf[b,f,c]) * data[b,t,c,f]
// grid = (64, B), 256 threads, 16 t per block, thread f-strided.
// ---------------------------------------------------------------------------
__global__ __launch_bounds__(256)
void apply_kernel(const float2* __restrict__ data, float2* __restrict__ out) {
    int b = blockIdx.y;
    int t0 = blockIdx.x * 16;
    int tid = threadIdx.x;
    int fa = tid;
    int fb = tid + 256;
    bool hasC = (tid == 0);
    int fc = 512;

    float2 cba[8], cbb[8], cbc[8];
    const float2* bfb = g_bf + (size_t)b * NF * NC;
#pragma unroll
    for (int c = 0; c < 8; c++) {
        float2 v = bfb[fa * NC + c]; cba[c] = make_float2(v.x, -v.y);
        float2 w = bfb[fb * NC + c]; cbb[c] = make_float2(w.x, -w.y);
    }
    if (hasC) {
#pragma unroll
        for (int c = 0; c < 8; c++) {
            float2 v = bfb[fc * NC + c]; cbc[c] = make_float2(v.x, -v.y);
        }
    }

    for (int tl = 0; tl < 16; tl++) {
        int t = t0 + tl;
        const float2* base = data + ((size_t)(b * NT + t) * NC) * NF;
        float2 a0 = make_float2(0.f, 0.f);
        float2 a1 = make_float2(0.f, 0.f);
        float2 a2 = make_float2(0.f, 0.f);
#pragma unroll
        for (int c = 0; c < 8; c++) {
            float2 d0 = base[c * NF + fa];
            a0.x += cba[c].x * d0.x - cba[c].y * d0.y;
            a0.y += cba[c].x * d0.y + cba[c].y * d0.x;
            float2 d1 = base[c * NF + fb];
            a1.x += cbb[c].x * d1.x - cbb[c].y * d1.y;
            a1.y += cbb[c].x * d1.y + cbb[c].y * d1.x;
        }
        if (hasC) {
#pragma unroll
            for (int c = 0; c < 8; c++) {
                float2 d2 = base[c * NF + fc];
                a2.x += cbc[c].x * d2.x - cbc[c].y * d2.y;
                a2.y += cbc[c].x * d2.y + cbc[c].y * d2.x;
            }
        }
        float2* ob = out + (size_t)(b * NT + t) * NF;
        ob[fa] = a0;
        ob[fb] = a1;
        if (hasC) ob[fc] = a2;
    }
}

// ---------------------------------------------------------------------------
extern "C" void kernel_launch(void* const* d_in, const int* in_sizes, int n_in,
                              void* d_out, int out_size) {
    const float* data_ri     = (const float*)d_in[0];
    const float* mask_speech = (const float*)d_in[1];
    const float* mask_noise  = (const float*)d_in[2];
    const float* W_psd       = (const float*)d_in[3];
    const float* b_psd       = (const float*)d_in[4];
    const float* w_gvec      = (const float*)d_in[5];
    const float* b_gvec      = (const float*)d_in[6];
    (void)in_sizes; (void)n_in; (void)out_size;

    const float2* data2 = (const float2*)data_ri;
    float2* out2 = (float2*)d_out;

    mask_norm_kernel<<<NB * NF, 256>>>(mask_speech, mask_noise);
    psd_kernel<<<dim3(57, NB, NSPLIT), 288>>>(data2);
    combine_kernel<<<(NB * NF * 36 + 255) / 256, 256>>>();
    attn_kernel<<<NB * NC, 320>>>(W_psd, b_psd, w_gvec, b_gvec);
    {
        int total = NB * NF * 16;
        int blocks = (total + 255) / 256;
        mvdr_kernel<<<blocks, 256>>>();
    }
    apply_kernel<<<dim3(64, NB), 256>>>(data2, out2);
}